// round 12
// baseline (speedup 1.0000x reference)
#include <cuda_runtime.h>
#include <math.h>

// Branch-free fast tanh: 1 - 2/(1 + 2^(2*log2e*x)).
__device__ __forceinline__ float ftanh(float x) {
    float e;
    asm("ex2.approx.f32 %0, %1;" : "=f"(e) : "f"(x * 2.885390081777927f));
    float r;
    asm("rcp.approx.f32 %0, %1;" : "=f"(r) : "f"(e + 1.0f));
    return fmaf(-2.0f, r, 1.0f);
}

// Branch-free fast atan2, abs err ~1e-4 rad.
__device__ __forceinline__ float fatan2(float y, float x) {
    float ax = fabsf(x), ay = fabsf(y);
    float mn = fminf(ax, ay), mx = fmaxf(ax, ay);
    float r;
    asm("rcp.approx.f32 %0, %1;" : "=f"(r) : "f"(mx));
    float t = mn * r;
    float s = t * t;
    float p = fmaf(s, fmaf(s, fmaf(s, fmaf(s, 0.0208351f, -0.085133f),
                                   0.180141f), -0.3302995f), 0.999866f);
    float a = t * p;
    a = (ay > ax) ? (1.57079632679f - a) : a;
    a = (x < 0.f) ? (3.14159265359f - a) : a;
    return (y < 0.f) ? -a : a;
}

#define FULLM 0xffffffffu

// Shared weight arena offsets (floats). c1w/d4w 16B-aligned for float4 loads.
#define O_C1W 0      // 216
#define O_D4W 216    // 252
#define O_C1B 468    // 6
#define O_C2W 474    // 72
#define O_C2B 546    // 4
#define O_C3W 550    // 48
#define O_C3B 598    // 4
#define O_E1W 602    // 24
#define O_E1B 626    // 4
#define O_E2W 630    // 16
#define O_E2B 646    // 4
#define O_D1W 650    // 48
#define O_D1B 698    // 4
#define O_D2W 702    // 24
#define O_D2B 726    // 2
#define O_D3W 728    // 12
#define O_D3B 740    // 2
#define O_D4B 742    // 6
#define W_TOTAL 748

__global__ __launch_bounds__(128, 1)
void policy_kernel(const float* __restrict__ x,
                   const float* __restrict__ c1w, const float* __restrict__ c1b,
                   const float* __restrict__ c2w, const float* __restrict__ c2b,
                   const float* __restrict__ c3w, const float* __restrict__ c3b,
                   const float* __restrict__ e1w, const float* __restrict__ e1b,
                   const float* __restrict__ e2w, const float* __restrict__ e2b,
                   const float* __restrict__ d1w, const float* __restrict__ d1b,
                   const float* __restrict__ d2w, const float* __restrict__ d2b,
                   const float* __restrict__ d3w, const float* __restrict__ d3b,
                   const float* __restrict__ d4w, const float* __restrict__ d4b,
                   float* __restrict__ out)
{
    __shared__ __align__(16) float W[W_TOTAL];
    __shared__ float jcat[12][15];
    __shared__ float c1s[6][13];
    __shared__ float dc3[2][15];
    __shared__ float part[90];

    const int tid = threadIdx.x;

    // ==== Stage 0 (block-wide): prefetch weights + build jcat ====
    float qw_r = 0.f, qx_r = 0.f, qy_r = 0.f, qz_r = 0.f, x100_r = 0.f;
    if (tid == 31) {
        qw_r = x[3]; qx_r = x[4]; qy_r = x[5]; qz_r = x[6]; x100_r = x[100];
    }

    if (tid < 54) ((float4*)&W[O_C1W])[tid] = ((const float4*)c1w)[tid];
    if (tid < 63) ((float4*)&W[O_D4W])[tid] = ((const float4*)d4w)[tid];
    #define CP(off, src, n) for (int i = tid; i < (n); i += 128) W[(off) + i] = src[i];
    CP(O_C1B, c1b, 6)
    CP(O_C2W, c2w, 72)  CP(O_C2B, c2b, 4)
    CP(O_C3W, c3w, 48)  CP(O_C3B, c3b, 4)
    CP(O_E1W, e1w, 24)  CP(O_E1B, e1b, 4)
    CP(O_E2W, e2w, 16)  CP(O_E2B, e2b, 4)
    CP(O_D1W, d1w, 48)  CP(O_D1B, d1b, 4)
    CP(O_D2W, d2w, 24)  CP(O_D2B, d2b, 2)
    CP(O_D3W, d3w, 12)  CP(O_D3B, d3b, 2)
    CP(O_D4B, d4b, 6)
    #undef CP

    for (int idx = tid; idx < 180; idx += 128) {
        int c = idx / 15, l = idx % 15;
        float v;
        if (c < 6) {
            int f = c * 15 + l;
            v = (f < 2) ? 0.f : x[f + 5];
        } else {
            int f = (c - 6) * 15 + l;
            v = (f < 2) ? 0.f : x[f + 99];
        }
        jcat[c][l] = v;
    }
    __syncthreads();   // B1

    if (tid < 32) {
        // ======== WARP 0: chain; middle stages are register+shuffle only ========
        const int lane = tid;

        // psi on lane 31 (slack lane), kept in registers
        float psi_r = 0.f, xv_r = 0.f;
        if (lane == 31) {
            psi_r = fatan2(qz_r, qw_r) - fatan2(-qx_r, qy_r);
            xv_r = x100_r;
        }

        // ---- conv1: (12,15)->(6,13), 4-way acc split -> c1s smem ----
        for (int idx = lane; idx < 78; idx += 32) {
            int o = idx / 13, t = idx % 13;
            const float* w = &W[O_C1W + o * 36];
            float a0 = W[O_C1B + o], a1 = 0.f, a2 = 0.f, a3 = 0.f;
            #pragma unroll
            for (int j = 0; j < 3; j++) {
                a0 = fmaf(w[0*3+j], jcat[0][t+j], a0); a0 = fmaf(w[1*3+j], jcat[1][t+j], a0); a0 = fmaf(w[2*3+j],  jcat[2][t+j],  a0);
                a1 = fmaf(w[3*3+j], jcat[3][t+j], a1); a1 = fmaf(w[4*3+j], jcat[4][t+j], a1); a1 = fmaf(w[5*3+j],  jcat[5][t+j],  a1);
                a2 = fmaf(w[6*3+j], jcat[6][t+j], a2); a2 = fmaf(w[7*3+j], jcat[7][t+j], a2); a2 = fmaf(w[8*3+j],  jcat[8][t+j],  a2);
                a3 = fmaf(w[9*3+j], jcat[9][t+j], a3); a3 = fmaf(w[10*3+j],jcat[10][t+j],a3); a3 = fmaf(w[11*3+j], jcat[11][t+j], a3);
            }
            c1s[o][t] = ftanh((a0 + a1) + (a2 + a3));
        }
        __syncwarp();   // only warp-level barrier in the whole middle

        // ---- pool 13->5 into registers: lane l = (o=l/5, i=l%5), l<30 ----
        float dssv;
        {
            int o = lane / 5; o = (o > 5) ? 5 : o;
            int i = lane % 5;
            int s = (i * 13) / 5;
            int e = ((i + 1) * 13 + 4) / 5;
            float acc = 0.f;
            for (int l = s; l < e; l++) acc += c1s[o][l];
            dssv = acc / (float)(e - s);
        }

        // ---- conv2 via shfl: lane l = (o=l/3, t=l%3), l<12 meaningful ----
        float c2v;
        {
            int o = lane / 3; o = (o > 3) ? 3 : o;
            int t = lane % 3;
            float acc = W[O_C2B + o];
            #pragma unroll
            for (int i = 0; i < 6; i++)
                #pragma unroll
                for (int j = 0; j < 3; j++) {
                    float v = __shfl_sync(FULLM, dssv, i * 5 + t + j);
                    acc = fmaf(W[O_C2W + o * 18 + i * 3 + j], v, acc);
                }
            c2v = ftanh(acc);
        }

        // ---- conv3 via shfl: lane o<4 ----
        float c3v;
        {
            int o = (lane > 3) ? 3 : lane;
            float acc = W[O_C3B + o];
            #pragma unroll
            for (int i = 0; i < 4; i++)
                #pragma unroll
                for (int j = 0; j < 3; j++) {
                    float v = __shfl_sync(FULLM, c2v, i * 3 + j);
                    acc = fmaf(W[O_C3W + o * 12 + i * 3 + j], v, acc);
                }
            c3v = ftanh(acc);
        }

        // ---- emb1 via shfl (6 inputs: c3v lanes 0-3, psi/x100 from lane 31) ----
        float e1v;
        {
            float em0 = __shfl_sync(FULLM, c3v, 0);
            float em1 = __shfl_sync(FULLM, c3v, 1);
            float em2 = __shfl_sync(FULLM, c3v, 2);
            float em3 = __shfl_sync(FULLM, c3v, 3);
            float em4 = __shfl_sync(FULLM, psi_r, 31);
            float em5 = __shfl_sync(FULLM, xv_r, 31);
            int o = (lane > 3) ? 3 : lane;
            float a0 = W[O_E1B + o], a1 = 0.f;
            a0 = fmaf(W[O_E1W + o*6 + 0], em0, a0);
            a0 = fmaf(W[O_E1W + o*6 + 1], em1, a0);
            a0 = fmaf(W[O_E1W + o*6 + 2], em2, a0);
            a1 = fmaf(W[O_E1W + o*6 + 3], em3, a1);
            a1 = fmaf(W[O_E1W + o*6 + 4], em4, a1);
            a1 = fmaf(W[O_E1W + o*6 + 5], em5, a1);
            e1v = ftanh(a0 + a1);
        }

        // ---- emb2 via shfl ----
        float e2v;
        {
            float s0 = __shfl_sync(FULLM, e1v, 0);
            float s1 = __shfl_sync(FULLM, e1v, 1);
            float s2 = __shfl_sync(FULLM, e1v, 2);
            float s3 = __shfl_sync(FULLM, e1v, 3);
            int o = (lane > 3) ? 3 : lane;
            float a0 = W[O_E2B + o], a1 = 0.f;
            a0 = fmaf(W[O_E2W + o*4 + 0], s0, a0);
            a0 = fmaf(W[O_E2W + o*4 + 1], s1, a0);
            a1 = fmaf(W[O_E2W + o*4 + 2], s2, a1);
            a1 = fmaf(W[O_E2W + o*4 + 3], s3, a1);
            e2v = ftanh(a0 + a1);
        }

        // ---- dec1 via shfl: lane l = (o=l/3, t=l%3), l<12 ----
        float dc1v;
        {
            float s0 = __shfl_sync(FULLM, e2v, 0);
            float s1 = __shfl_sync(FULLM, e2v, 1);
            float s2 = __shfl_sync(FULLM, e2v, 2);
            float s3 = __shfl_sync(FULLM, e2v, 3);
            int o = lane / 3; o = (o > 3) ? 3 : o;
            int t = lane % 3;
            float a0 = W[O_D1B + o], a1 = 0.f;
            a0 = fmaf(W[O_D1W + 0*12 + o*3 + t], s0, a0);
            a0 = fmaf(W[O_D1W + 1*12 + o*3 + t], s1, a0);
            a1 = fmaf(W[O_D1W + 2*12 + o*3 + t], s2, a1);
            a1 = fmaf(W[O_D1W + 3*12 + o*3 + t], s3, a1);
            dc1v = ftanh(a0 + a1);
        }

        // ---- dec2 via shfl: lane l = (o=l/5, t=l%5), l<10 ----
        float dc2v;
        {
            int o = lane / 5; o = (o > 1) ? 1 : o;
            int t = lane % 5;
            float acc = W[O_D2B + o];
            #pragma unroll
            for (int m = 0; m < 3; m++) {
                int s = t - m;
                bool ok = (s >= 0 && s < 3);
                int sc = ok ? s : 0;
                #pragma unroll
                for (int i = 0; i < 4; i++) {
                    float v = __shfl_sync(FULLM, dc1v, i * 3 + sc);
                    if (ok) acc = fmaf(W[O_D2W + i*6 + o*3 + m], v, acc);
                }
            }
            dc2v = ftanh(acc);
        }

        // ---- upsample + dec3 via shfl: lane l = (o=l/15, t=l%15), l<30 ----
        {
            int o = lane / 15; o = (o > 1) ? 1 : o;
            int t = lane % 15;
            float acc = W[O_D3B + o];
            #pragma unroll
            for (int m = 0; m < 3; m++) {
                int s = t - m;
                bool ok = (s >= 0 && s < 13);
                int sc = ok ? s : 0;
                int u = (sc * 5) / 13;                 // UP index, arithmetic
                float v0 = __shfl_sync(FULLM, dc2v, u);
                float v1 = __shfl_sync(FULLM, dc2v, 5 + u);
                if (ok) {
                    acc = fmaf(W[O_D3W + 0*6 + o*3 + m], v0, acc);
                    acc = fmaf(W[O_D3W + 1*6 + o*3 + m], v1, acc);
                }
            }
            if (lane < 30) dc3[o][t] = ftanh(acc);
        }
    } else if (tid < 122) {
        // ======== WARPS 1-3: dec4 jcat-partials (channels 2..13), one each ====
        int idx = tid - 32;
        int o = idx / 15, t = idx % 15;
        float a0 = W[O_D4B + o], a1 = 0.f, a2 = 0.f;
        #pragma unroll
        for (int m = 0; m < 3; m++) {
            int s = t + 1 - m;
            if (s >= 0 && s < 15) {
                a0 = fmaf(W[O_D4W + 2*18  + o*3 + m], jcat[0][s],  a0);
                a0 = fmaf(W[O_D4W + 3*18  + o*3 + m], jcat[1][s],  a0);
                a0 = fmaf(W[O_D4W + 4*18  + o*3 + m], jcat[2][s],  a0);
                a0 = fmaf(W[O_D4W + 5*18  + o*3 + m], jcat[3][s],  a0);
                a1 = fmaf(W[O_D4W + 6*18  + o*3 + m], jcat[4][s],  a1);
                a1 = fmaf(W[O_D4W + 7*18  + o*3 + m], jcat[5][s],  a1);
                a1 = fmaf(W[O_D4W + 8*18  + o*3 + m], jcat[6][s],  a1);
                a1 = fmaf(W[O_D4W + 9*18  + o*3 + m], jcat[7][s],  a1);
                a2 = fmaf(W[O_D4W + 10*18 + o*3 + m], jcat[8][s],  a2);
                a2 = fmaf(W[O_D4W + 11*18 + o*3 + m], jcat[9][s],  a2);
                a2 = fmaf(W[O_D4W + 12*18 + o*3 + m], jcat[10][s], a2);
                a2 = fmaf(W[O_D4W + 13*18 + o*3 + m], jcat[11][s], a2);
            }
        }
        part[idx] = (a0 + a1) + a2;
    }
    __syncthreads();   // B2

    // ==== dec4 final: add 2-channel dc3 contribution and store ====
    if (tid < 90) {
        int o = tid / 15, t = tid % 15;
        float acc = part[tid];
        #pragma unroll
        for (int m = 0; m < 3; m++) {
            int s = t + 1 - m;
            if (s >= 0 && s < 15) {
                acc = fmaf(W[O_D4W + 0*18 + o*3 + m], dc3[0][s], acc);
                acc = fmaf(W[O_D4W + 1*18 + o*3 + m], dc3[1][s], acc);
            }
        }
        if (tid >= 2) out[tid - 2] = acc;
    }
}

extern "C" void kernel_launch(void* const* d_in, const int* in_sizes, int n_in,
                              void* d_out, int out_size) {
    (void)in_sizes; (void)n_in; (void)out_size;
    policy_kernel<<<1, 128>>>(
        (const float*)d_in[0],
        (const float*)d_in[1],  (const float*)d_in[2],
        (const float*)d_in[3],  (const float*)d_in[4],
        (const float*)d_in[5],  (const float*)d_in[6],
        (const float*)d_in[7],  (const float*)d_in[8],
        (const float*)d_in[9],  (const float*)d_in[10],
        (const float*)d_in[11], (const float*)d_in[12],
        (const float*)d_in[13], (const float*)d_in[14],
        (const float*)d_in[15], (const float*)d_in[16],
        (const float*)d_in[17], (const float*)d_in[18],
        (float*)d_out);
}

// round 13
// speedup vs baseline: 1.2799x; 1.2799x over previous
#include <cuda_runtime.h>
#include <math.h>

// HW tanh (sm_75+): single MUFU op, ~16 cyc, ~1e-6 rel err.
__device__ __forceinline__ float ftanh(float x) {
    float r;
    asm("tanh.approx.f32 %0, %1;" : "=f"(r) : "f"(x));
    return r;
}

// Branch-free fast atan2, abs err ~1e-4 rad.
__device__ __forceinline__ float fatan2(float y, float x) {
    float ax = fabsf(x), ay = fabsf(y);
    float mn = fminf(ax, ay), mx = fmaxf(ax, ay);
    float r;
    asm("rcp.approx.f32 %0, %1;" : "=f"(r) : "f"(mx));
    float t = mn * r;
    float s = t * t;
    float p = fmaf(s, fmaf(s, fmaf(s, fmaf(s, 0.0208351f, -0.085133f),
                                   0.180141f), -0.3302995f), 0.999866f);
    float a = t * p;
    a = (ay > ax) ? (1.57079632679f - a) : a;
    a = (x < 0.f) ? (3.14159265359f - a) : a;
    return (y < 0.f) ? -a : a;
}

#define FULLM 0xffffffffu

// Shared weight arena offsets (floats). c1w/d4w 16B-aligned for float4 loads.
#define O_C1W 0      // 216
#define O_D4W 216    // 252
#define O_C1B 468    // 6
#define O_C2W 474    // 72
#define O_C2B 546    // 4
#define O_C3W 550    // 48
#define O_C3B 598    // 4
#define O_E1W 602    // 24
#define O_E1B 626    // 4
#define O_E2W 630    // 16
#define O_E2B 646    // 4
#define O_D1W 650    // 48
#define O_D1B 698    // 4
#define O_D2W 702    // 24
#define O_D2B 726    // 2
#define O_D3W 728    // 12
#define O_D3B 740    // 2
#define O_D4B 742    // 6
#define W_TOTAL 748

__global__ __launch_bounds__(128, 1)
void policy_kernel(const float* __restrict__ x,
                   const float* __restrict__ c1w, const float* __restrict__ c1b,
                   const float* __restrict__ c2w, const float* __restrict__ c2b,
                   const float* __restrict__ c3w, const float* __restrict__ c3b,
                   const float* __restrict__ e1w, const float* __restrict__ e1b,
                   const float* __restrict__ e2w, const float* __restrict__ e2b,
                   const float* __restrict__ d1w, const float* __restrict__ d1b,
                   const float* __restrict__ d2w, const float* __restrict__ d2b,
                   const float* __restrict__ d3w, const float* __restrict__ d3b,
                   const float* __restrict__ d4w, const float* __restrict__ d4b,
                   float* __restrict__ out)
{
    __shared__ __align__(16) float W[W_TOTAL];
    __shared__ float jcat[12][15];
    __shared__ float c1s[6][13];
    __shared__ float dc3[2][15];
    __shared__ float part[90];

    const int tid = threadIdx.x;

    // ==== Stage 0 (block-wide): prefetch weights + build jcat ====
    float qw_r = 0.f, qx_r = 0.f, qy_r = 0.f, qz_r = 0.f, x100_r = 0.f;
    if (tid == 31) {
        qw_r = x[3]; qx_r = x[4]; qy_r = x[5]; qz_r = x[6]; x100_r = x[100];
    }

    if (tid < 54) ((float4*)&W[O_C1W])[tid] = ((const float4*)c1w)[tid];
    if (tid < 63) ((float4*)&W[O_D4W])[tid] = ((const float4*)d4w)[tid];
    #define CP(off, src, n) for (int i = tid; i < (n); i += 128) W[(off) + i] = src[i];
    CP(O_C1B, c1b, 6)
    CP(O_C2W, c2w, 72)  CP(O_C2B, c2b, 4)
    CP(O_C3W, c3w, 48)  CP(O_C3B, c3b, 4)
    CP(O_E1W, e1w, 24)  CP(O_E1B, e1b, 4)
    CP(O_E2W, e2w, 16)  CP(O_E2B, e2b, 4)
    CP(O_D1W, d1w, 48)  CP(O_D1B, d1b, 4)
    CP(O_D2W, d2w, 24)  CP(O_D2B, d2b, 2)
    CP(O_D3W, d3w, 12)  CP(O_D3B, d3b, 2)
    CP(O_D4B, d4b, 6)
    #undef CP

    for (int idx = tid; idx < 180; idx += 128) {
        int c = idx / 15, l = idx % 15;
        float v;
        if (c < 6) {
            int f = c * 15 + l;
            v = (f < 2) ? 0.f : x[f + 5];
        } else {
            int f = (c - 6) * 15 + l;
            v = (f < 2) ? 0.f : x[f + 99];
        }
        jcat[c][l] = v;
    }
    __syncthreads();   // B1

    if (tid < 32) {
        // ======== WARP 0: chain; middle stages register+shuffle only ========
        const int lane = tid;

        // psi on lane 31 (slack lane), kept in registers
        float psi_r = 0.f, xv_r = 0.f;
        if (lane == 31) {
            psi_r = fatan2(qz_r, qw_r) - fatan2(-qx_r, qy_r);
            xv_r = x100_r;
        }

        // ---- conv1: (12,15)->(6,13), 4-way acc split -> c1s smem ----
        for (int idx = lane; idx < 78; idx += 32) {
            int o = idx / 13, t = idx % 13;
            const float* w = &W[O_C1W + o * 36];
            float a0 = W[O_C1B + o], a1 = 0.f, a2 = 0.f, a3 = 0.f;
            #pragma unroll
            for (int j = 0; j < 3; j++) {
                a0 = fmaf(w[0*3+j], jcat[0][t+j], a0); a0 = fmaf(w[1*3+j], jcat[1][t+j], a0); a0 = fmaf(w[2*3+j],  jcat[2][t+j],  a0);
                a1 = fmaf(w[3*3+j], jcat[3][t+j], a1); a1 = fmaf(w[4*3+j], jcat[4][t+j], a1); a1 = fmaf(w[5*3+j],  jcat[5][t+j],  a1);
                a2 = fmaf(w[6*3+j], jcat[6][t+j], a2); a2 = fmaf(w[7*3+j], jcat[7][t+j], a2); a2 = fmaf(w[8*3+j],  jcat[8][t+j],  a2);
                a3 = fmaf(w[9*3+j], jcat[9][t+j], a3); a3 = fmaf(w[10*3+j],jcat[10][t+j],a3); a3 = fmaf(w[11*3+j], jcat[11][t+j], a3);
            }
            c1s[o][t] = ftanh((a0 + a1) + (a2 + a3));
        }
        __syncwarp();

        // ---- pool 13->5 into registers: lane l = (o=l/5, i=l%5) ----
        float dssv;
        {
            int o = lane / 5; o = (o > 5) ? 5 : o;
            int i = lane % 5;
            int s = (i * 13) / 5;
            int e = ((i + 1) * 13 + 4) / 5;
            float acc = 0.f;
            for (int l = s; l < e; l++) acc += c1s[o][l];
            dssv = acc / (float)(e - s);
        }

        // ---- conv2 via shfl: lane l = (o=l/3, t=l%3) ----
        float c2v;
        {
            int o = lane / 3; o = (o > 3) ? 3 : o;
            int t = lane % 3;
            float acc = W[O_C2B + o];
            #pragma unroll
            for (int i = 0; i < 6; i++)
                #pragma unroll
                for (int j = 0; j < 3; j++) {
                    float v = __shfl_sync(FULLM, dssv, i * 5 + t + j);
                    acc = fmaf(W[O_C2W + o * 18 + i * 3 + j], v, acc);
                }
            c2v = ftanh(acc);
        }

        // ---- conv3 via shfl ----
        float c3v;
        {
            int o = (lane > 3) ? 3 : lane;
            float acc = W[O_C3B + o];
            #pragma unroll
            for (int i = 0; i < 4; i++)
                #pragma unroll
                for (int j = 0; j < 3; j++) {
                    float v = __shfl_sync(FULLM, c2v, i * 3 + j);
                    acc = fmaf(W[O_C3W + o * 12 + i * 3 + j], v, acc);
                }
            c3v = ftanh(acc);
        }

        // ---- emb1 via shfl ----
        float e1v;
        {
            float em0 = __shfl_sync(FULLM, c3v, 0);
            float em1 = __shfl_sync(FULLM, c3v, 1);
            float em2 = __shfl_sync(FULLM, c3v, 2);
            float em3 = __shfl_sync(FULLM, c3v, 3);
            float em4 = __shfl_sync(FULLM, psi_r, 31);
            float em5 = __shfl_sync(FULLM, xv_r, 31);
            int o = (lane > 3) ? 3 : lane;
            float a0 = W[O_E1B + o], a1 = 0.f;
            a0 = fmaf(W[O_E1W + o*6 + 0], em0, a0);
            a0 = fmaf(W[O_E1W + o*6 + 1], em1, a0);
            a0 = fmaf(W[O_E1W + o*6 + 2], em2, a0);
            a1 = fmaf(W[O_E1W + o*6 + 3], em3, a1);
            a1 = fmaf(W[O_E1W + o*6 + 4], em4, a1);
            a1 = fmaf(W[O_E1W + o*6 + 5], em5, a1);
            e1v = ftanh(a0 + a1);
        }

        // ---- emb2 via shfl ----
        float e2v;
        {
            float s0 = __shfl_sync(FULLM, e1v, 0);
            float s1 = __shfl_sync(FULLM, e1v, 1);
            float s2 = __shfl_sync(FULLM, e1v, 2);
            float s3 = __shfl_sync(FULLM, e1v, 3);
            int o = (lane > 3) ? 3 : lane;
            float a0 = W[O_E2B + o], a1 = 0.f;
            a0 = fmaf(W[O_E2W + o*4 + 0], s0, a0);
            a0 = fmaf(W[O_E2W + o*4 + 1], s1, a0);
            a1 = fmaf(W[O_E2W + o*4 + 2], s2, a1);
            a1 = fmaf(W[O_E2W + o*4 + 3], s3, a1);
            e2v = ftanh(a0 + a1);
        }

        // ---- dec1 via shfl: lane l = (o=l/3, t=l%3) ----
        float dc1v;
        {
            float s0 = __shfl_sync(FULLM, e2v, 0);
            float s1 = __shfl_sync(FULLM, e2v, 1);
            float s2 = __shfl_sync(FULLM, e2v, 2);
            float s3 = __shfl_sync(FULLM, e2v, 3);
            int o = lane / 3; o = (o > 3) ? 3 : o;
            int t = lane % 3;
            float a0 = W[O_D1B + o], a1 = 0.f;
            a0 = fmaf(W[O_D1W + 0*12 + o*3 + t], s0, a0);
            a0 = fmaf(W[O_D1W + 1*12 + o*3 + t], s1, a0);
            a1 = fmaf(W[O_D1W + 2*12 + o*3 + t], s2, a1);
            a1 = fmaf(W[O_D1W + 3*12 + o*3 + t], s3, a1);
            dc1v = ftanh(a0 + a1);
        }

        // ---- dec2 via shfl: lane l = (o=l/5, t=l%5) ----
        float dc2v;
        {
            int o = lane / 5; o = (o > 1) ? 1 : o;
            int t = lane % 5;
            float acc = W[O_D2B + o];
            #pragma unroll
            for (int m = 0; m < 3; m++) {
                int s = t - m;
                bool ok = (s >= 0 && s < 3);
                int sc = ok ? s : 0;
                #pragma unroll
                for (int i = 0; i < 4; i++) {
                    float v = __shfl_sync(FULLM, dc1v, i * 3 + sc);
                    if (ok) acc = fmaf(W[O_D2W + i*6 + o*3 + m], v, acc);
                }
            }
            dc2v = ftanh(acc);
        }

        // ---- upsample + dec3 via shfl: lane l = (o=l/15, t=l%15) ----
        {
            int o = lane / 15; o = (o > 1) ? 1 : o;
            int t = lane % 15;
            float acc = W[O_D3B + o];
            #pragma unroll
            for (int m = 0; m < 3; m++) {
                int s = t - m;
                bool ok = (s >= 0 && s < 13);
                int sc = ok ? s : 0;
                int u = (sc * 5) / 13;
                float v0 = __shfl_sync(FULLM, dc2v, u);
                float v1 = __shfl_sync(FULLM, dc2v, 5 + u);
                if (ok) {
                    acc = fmaf(W[O_D3W + 0*6 + o*3 + m], v0, acc);
                    acc = fmaf(W[O_D3W + 1*6 + o*3 + m], v1, acc);
                }
            }
            if (lane < 30) dc3[o][t] = ftanh(acc);
        }
    } else if (tid < 122) {
        // ======== WARPS 1-3: dec4 jcat-partials (channels 2..13) ========
        int idx = tid - 32;
        int o = idx / 15, t = idx % 15;
        float a0 = W[O_D4B + o], a1 = 0.f, a2 = 0.f;
        #pragma unroll
        for (int m = 0; m < 3; m++) {
            int s = t + 1 - m;
            if (s >= 0 && s < 15) {
                a0 = fmaf(W[O_D4W + 2*18  + o*3 + m], jcat[0][s],  a0);
                a0 = fmaf(W[O_D4W + 3*18  + o*3 + m], jcat[1][s],  a0);
                a0 = fmaf(W[O_D4W + 4*18  + o*3 + m], jcat[2][s],  a0);
                a0 = fmaf(W[O_D4W + 5*18  + o*3 + m], jcat[3][s],  a0);
                a1 = fmaf(W[O_D4W + 6*18  + o*3 + m], jcat[4][s],  a1);
                a1 = fmaf(W[O_D4W + 7*18  + o*3 + m], jcat[5][s],  a1);
                a1 = fmaf(W[O_D4W + 8*18  + o*3 + m], jcat[6][s],  a1);
                a1 = fmaf(W[O_D4W + 9*18  + o*3 + m], jcat[7][s],  a1);
                a2 = fmaf(W[O_D4W + 10*18 + o*3 + m], jcat[8][s],  a2);
                a2 = fmaf(W[O_D4W + 11*18 + o*3 + m], jcat[9][s],  a2);
                a2 = fmaf(W[O_D4W + 12*18 + o*3 + m], jcat[10][s], a2);
                a2 = fmaf(W[O_D4W + 13*18 + o*3 + m], jcat[11][s], a2);
            }
        }
        part[idx] = (a0 + a1) + a2;
    }
    __syncthreads();   // B2

    // ==== dec4 final: add 2-channel dc3 contribution and store ====
    if (tid < 90) {
        int o = tid / 15, t = tid % 15;
        float acc = part[tid];
        #pragma unroll
        for (int m = 0; m < 3; m++) {
            int s = t + 1 - m;
            if (s >= 0 && s < 15) {
                acc = fmaf(W[O_D4W + 0*18 + o*3 + m], dc3[0][s], acc);
                acc = fmaf(W[O_D4W + 1*18 + o*3 + m], dc3[1][s], acc);
            }
        }
        if (tid >= 2) out[tid - 2] = acc;
    }
}

extern "C" void kernel_launch(void* const* d_in, const int* in_sizes, int n_in,
                              void* d_out, int out_size) {
    (void)in_sizes; (void)n_in; (void)out_size;
    policy_kernel<<<1, 128>>>(
        (const float*)d_in[0],
        (const float*)d_in[1],  (const float*)d_in[2],
        (const float*)d_in[3],  (const float*)d_in[4],
        (const float*)d_in[5],  (const float*)d_in[6],
        (const float*)d_in[7],  (const float*)d_in[8],
        (const float*)d_in[9],  (const float*)d_in[10],
        (const float*)d_in[11], (const float*)d_in[12],
        (const float*)d_in[13], (const float*)d_in[14],
        (const float*)d_in[15], (const float*)d_in[16],
        (const float*)d_in[17], (const float*)d_in[18],
        (float*)d_out);
}

// round 14
// speedup vs baseline: 1.6490x; 1.2885x over previous
#include <cuda_runtime.h>
#include <math.h>

// HW tanh (sm_75+): single MUFU op, ~16 cyc, ~1e-6 rel err.
__device__ __forceinline__ float ftanh(float x) {
    float r;
    asm("tanh.approx.f32 %0, %1;" : "=f"(r) : "f"(x));
    return r;
}

// Branch-free fast atan2, abs err ~1e-4 rad.
__device__ __forceinline__ float fatan2(float y, float x) {
    float ax = fabsf(x), ay = fabsf(y);
    float mn = fminf(ax, ay), mx = fmaxf(ax, ay);
    float r;
    asm("rcp.approx.f32 %0, %1;" : "=f"(r) : "f"(mx));
    float t = mn * r;
    float s = t * t;
    float p = fmaf(s, fmaf(s, fmaf(s, fmaf(s, 0.0208351f, -0.085133f),
                                   0.180141f), -0.3302995f), 0.999866f);
    float a = t * p;
    a = (ay > ax) ? (1.57079632679f - a) : a;
    a = (x < 0.f) ? (3.14159265359f - a) : a;
    return (y < 0.f) ? -a : a;
}

#define FULLM 0xffffffffu

// Shared weight arena offsets (floats). c1w/d4w 16B-aligned for float4 loads.
#define O_C1W 0      // 216
#define O_D4W 216    // 252
#define O_C1B 468    // 6
#define O_C2W 474    // 72
#define O_C2B 546    // 4
#define O_C3W 550    // 48
#define O_C3B 598    // 4
#define O_E1W 602    // 24
#define O_E1B 626    // 4
#define O_E2W 630    // 16
#define O_E2B 646    // 4
#define O_D1W 650    // 48
#define O_D1B 698    // 4
#define O_D2W 702    // 24
#define O_D2B 726    // 2
#define O_D3W 728    // 12
#define O_D3B 740    // 2
#define O_D4B 742    // 6
#define W_TOTAL 748

__global__ __launch_bounds__(128, 1)
void policy_kernel(const float* __restrict__ x,
                   const float* __restrict__ c1w, const float* __restrict__ c1b,
                   const float* __restrict__ c2w, const float* __restrict__ c2b,
                   const float* __restrict__ c3w, const float* __restrict__ c3b,
                   const float* __restrict__ e1w, const float* __restrict__ e1b,
                   const float* __restrict__ e2w, const float* __restrict__ e2b,
                   const float* __restrict__ d1w, const float* __restrict__ d1b,
                   const float* __restrict__ d2w, const float* __restrict__ d2b,
                   const float* __restrict__ d3w, const float* __restrict__ d3b,
                   const float* __restrict__ d4w, const float* __restrict__ d4b,
                   float* __restrict__ out)
{
    __shared__ __align__(16) float W[W_TOTAL];
    __shared__ float jcat[12][15];
    __shared__ float c1s[6][13];
    __shared__ float embin45[2];   // [psi, x100]
    __shared__ float dc3[2][15];
    __shared__ float part[90];

    const int tid = threadIdx.x;

    // ==== Stage 0 (block-wide): prefetch weights + build jcat ====
    float qw_r = 0.f, qx_r = 0.f, qy_r = 0.f, qz_r = 0.f, x100_r = 0.f;
    if (tid == 127) {   // psi inputs on warp 3 (idle during conv1)
        qw_r = x[3]; qx_r = x[4]; qy_r = x[5]; qz_r = x[6]; x100_r = x[100];
    }

    if (tid < 54) ((float4*)&W[O_C1W])[tid] = ((const float4*)c1w)[tid];
    if (tid < 63) ((float4*)&W[O_D4W])[tid] = ((const float4*)d4w)[tid];
    #define CP(off, src, n) for (int i = tid; i < (n); i += 128) W[(off) + i] = src[i];
    CP(O_C1B, c1b, 6)
    CP(O_C2W, c2w, 72)  CP(O_C2B, c2b, 4)
    CP(O_C3W, c3w, 48)  CP(O_C3B, c3b, 4)
    CP(O_E1W, e1w, 24)  CP(O_E1B, e1b, 4)
    CP(O_E2W, e2w, 16)  CP(O_E2B, e2b, 4)
    CP(O_D1W, d1w, 48)  CP(O_D1B, d1b, 4)
    CP(O_D2W, d2w, 24)  CP(O_D2B, d2b, 2)
    CP(O_D3W, d3w, 12)  CP(O_D3B, d3b, 2)
    CP(O_D4B, d4b, 6)
    #undef CP

    for (int idx = tid; idx < 180; idx += 128) {
        int c = idx / 15, l = idx % 15;
        float v;
        if (c < 6) {
            int f = c * 15 + l;
            v = (f < 2) ? 0.f : x[f + 5];
        } else {
            int f = (c - 6) * 15 + l;
            v = (f < 2) ? 0.f : x[f + 99];
        }
        jcat[c][l] = v;
    }
    __syncthreads();   // B1

    // ==== conv1 cooperative: 78 threads (warps 0-2), one output each ====
    if (tid < 78) {
        int o = tid / 13, t = tid % 13;
        const float* w = &W[O_C1W + o * 36];
        float a0 = W[O_C1B + o], a1 = 0.f, a2 = 0.f, a3 = 0.f;
        #pragma unroll
        for (int j = 0; j < 3; j++) {
            a0 = fmaf(w[0*3+j], jcat[0][t+j], a0); a0 = fmaf(w[1*3+j], jcat[1][t+j], a0); a0 = fmaf(w[2*3+j],  jcat[2][t+j],  a0);
            a1 = fmaf(w[3*3+j], jcat[3][t+j], a1); a1 = fmaf(w[4*3+j], jcat[4][t+j], a1); a1 = fmaf(w[5*3+j],  jcat[5][t+j],  a1);
            a2 = fmaf(w[6*3+j], jcat[6][t+j], a2); a2 = fmaf(w[7*3+j], jcat[7][t+j], a2); a2 = fmaf(w[8*3+j],  jcat[8][t+j],  a2);
            a3 = fmaf(w[9*3+j], jcat[9][t+j], a3); a3 = fmaf(w[10*3+j],jcat[10][t+j],a3); a3 = fmaf(w[11*3+j], jcat[11][t+j], a3);
        }
        c1s[o][t] = ftanh((a0 + a1) + (a2 + a3));
    }
    // psi on tid 127, fully parallel with conv1
    if (tid == 127) {
        embin45[0] = fatan2(qz_r, qw_r) - fatan2(-qx_r, qy_r);
        embin45[1] = x100_r;
    }
    __syncthreads();   // B1b

    if (tid < 32) {
        // ======== WARP 0: middle chain, register+shuffle only ========
        const int lane = tid;

        // early-load psi inputs (hide LDS latency; needed at emb1)
        float em4 = embin45[0];
        float em5 = embin45[1];

        // ---- pool 13->5 into registers: lane l = (o=l/5, i=l%5) ----
        float dssv;
        {
            int o = lane / 5; o = (o > 5) ? 5 : o;
            int i = lane % 5;
            int s = (i * 13) / 5;
            int e = ((i + 1) * 13 + 4) / 5;
            float acc = 0.f;
            for (int l = s; l < e; l++) acc += c1s[o][l];
            dssv = acc / (float)(e - s);
        }

        // ---- conv2 via shfl: lane l = (o=l/3, t=l%3), 2-acc ----
        float c2v;
        {
            int o = lane / 3; o = (o > 3) ? 3 : o;
            int t = lane % 3;
            float a0 = W[O_C2B + o], a1 = 0.f;
            #pragma unroll
            for (int i = 0; i < 3; i++)
                #pragma unroll
                for (int j = 0; j < 3; j++) {
                    float v = __shfl_sync(FULLM, dssv, i * 5 + t + j);
                    a0 = fmaf(W[O_C2W + o * 18 + i * 3 + j], v, a0);
                }
            #pragma unroll
            for (int i = 3; i < 6; i++)
                #pragma unroll
                for (int j = 0; j < 3; j++) {
                    float v = __shfl_sync(FULLM, dssv, i * 5 + t + j);
                    a1 = fmaf(W[O_C2W + o * 18 + i * 3 + j], v, a1);
                }
            c2v = ftanh(a0 + a1);
        }

        // ---- conv3 via shfl, 2-acc ----
        float c3v;
        {
            int o = (lane > 3) ? 3 : lane;
            float a0 = W[O_C3B + o], a1 = 0.f;
            #pragma unroll
            for (int i = 0; i < 2; i++)
                #pragma unroll
                for (int j = 0; j < 3; j++) {
                    float v = __shfl_sync(FULLM, c2v, i * 3 + j);
                    a0 = fmaf(W[O_C3W + o * 12 + i * 3 + j], v, a0);
                }
            #pragma unroll
            for (int i = 2; i < 4; i++)
                #pragma unroll
                for (int j = 0; j < 3; j++) {
                    float v = __shfl_sync(FULLM, c2v, i * 3 + j);
                    a1 = fmaf(W[O_C3W + o * 12 + i * 3 + j], v, a1);
                }
            c3v = ftanh(a0 + a1);
        }

        // ---- emb1 via shfl ----
        float e1v;
        {
            float em0 = __shfl_sync(FULLM, c3v, 0);
            float em1 = __shfl_sync(FULLM, c3v, 1);
            float em2 = __shfl_sync(FULLM, c3v, 2);
            float em3 = __shfl_sync(FULLM, c3v, 3);
            int o = (lane > 3) ? 3 : lane;
            float a0 = W[O_E1B + o], a1 = 0.f;
            a0 = fmaf(W[O_E1W + o*6 + 0], em0, a0);
            a0 = fmaf(W[O_E1W + o*6 + 1], em1, a0);
            a0 = fmaf(W[O_E1W + o*6 + 2], em2, a0);
            a1 = fmaf(W[O_E1W + o*6 + 3], em3, a1);
            a1 = fmaf(W[O_E1W + o*6 + 4], em4, a1);
            a1 = fmaf(W[O_E1W + o*6 + 5], em5, a1);
            e1v = ftanh(a0 + a1);
        }

        // ---- emb2 via shfl ----
        float e2v;
        {
            float s0 = __shfl_sync(FULLM, e1v, 0);
            float s1 = __shfl_sync(FULLM, e1v, 1);
            float s2 = __shfl_sync(FULLM, e1v, 2);
            float s3 = __shfl_sync(FULLM, e1v, 3);
            int o = (lane > 3) ? 3 : lane;
            float a0 = W[O_E2B + o], a1 = 0.f;
            a0 = fmaf(W[O_E2W + o*4 + 0], s0, a0);
            a0 = fmaf(W[O_E2W + o*4 + 1], s1, a0);
            a1 = fmaf(W[O_E2W + o*4 + 2], s2, a1);
            a1 = fmaf(W[O_E2W + o*4 + 3], s3, a1);
            e2v = ftanh(a0 + a1);
        }

        // ---- dec1 via shfl: lane l = (o=l/3, t=l%3) ----
        float dc1v;
        {
            float s0 = __shfl_sync(FULLM, e2v, 0);
            float s1 = __shfl_sync(FULLM, e2v, 1);
            float s2 = __shfl_sync(FULLM, e2v, 2);
            float s3 = __shfl_sync(FULLM, e2v, 3);
            int o = lane / 3; o = (o > 3) ? 3 : o;
            int t = lane % 3;
            float a0 = W[O_D1B + o], a1 = 0.f;
            a0 = fmaf(W[O_D1W + 0*12 + o*3 + t], s0, a0);
            a0 = fmaf(W[O_D1W + 1*12 + o*3 + t], s1, a0);
            a1 = fmaf(W[O_D1W + 2*12 + o*3 + t], s2, a1);
            a1 = fmaf(W[O_D1W + 3*12 + o*3 + t], s3, a1);
            dc1v = ftanh(a0 + a1);
        }

        // ---- dec2 via shfl: lane l = (o=l/5, t=l%5), 2-acc ----
        float dc2v;
        {
            int o = lane / 5; o = (o > 1) ? 1 : o;
            int t = lane % 5;
            float a0 = W[O_D2B + o], a1 = 0.f;
            #pragma unroll
            for (int m = 0; m < 3; m++) {
                int s = t - m;
                bool ok = (s >= 0 && s < 3);
                int sc = ok ? s : 0;
                #pragma unroll
                for (int i = 0; i < 2; i++) {
                    float v = __shfl_sync(FULLM, dc1v, i * 3 + sc);
                    if (ok) a0 = fmaf(W[O_D2W + i*6 + o*3 + m], v, a0);
                }
                #pragma unroll
                for (int i = 2; i < 4; i++) {
                    float v = __shfl_sync(FULLM, dc1v, i * 3 + sc);
                    if (ok) a1 = fmaf(W[O_D2W + i*6 + o*3 + m], v, a1);
                }
            }
            dc2v = ftanh(a0 + a1);
        }

        // ---- upsample + dec3 via shfl: lane l = (o=l/15, t=l%15) ----
        {
            int o = lane / 15; o = (o > 1) ? 1 : o;
            int t = lane % 15;
            float a0 = W[O_D3B + o], a1 = 0.f;
            #pragma unroll
            for (int m = 0; m < 3; m++) {
                int s = t - m;
                bool ok = (s >= 0 && s < 13);
                int sc = ok ? s : 0;
                int u = (sc * 5) / 13;
                float v0 = __shfl_sync(FULLM, dc2v, u);
                float v1 = __shfl_sync(FULLM, dc2v, 5 + u);
                if (ok) {
                    a0 = fmaf(W[O_D3W + 0*6 + o*3 + m], v0, a0);
                    a1 = fmaf(W[O_D3W + 1*6 + o*3 + m], v1, a1);
                }
            }
            if (lane < 30) dc3[o][t] = ftanh(a0 + a1);
        }
    } else if (tid < 122) {
        // ======== WARPS 1-3: dec4 jcat-partials (channels 2..13) ========
        int idx = tid - 32;
        int o = idx / 15, t = idx % 15;
        float a0 = W[O_D4B + o], a1 = 0.f, a2 = 0.f;
        #pragma unroll
        for (int m = 0; m < 3; m++) {
            int s = t + 1 - m;
            if (s >= 0 && s < 15) {
                a0 = fmaf(W[O_D4W + 2*18  + o*3 + m], jcat[0][s],  a0);
                a0 = fmaf(W[O_D4W + 3*18  + o*3 + m], jcat[1][s],  a0);
                a0 = fmaf(W[O_D4W + 4*18  + o*3 + m], jcat[2][s],  a0);
                a0 = fmaf(W[O_D4W + 5*18  + o*3 + m], jcat[3][s],  a0);
                a1 = fmaf(W[O_D4W + 6*18  + o*3 + m], jcat[4][s],  a1);
                a1 = fmaf(W[O_D4W + 7*18  + o*3 + m], jcat[5][s],  a1);
                a1 = fmaf(W[O_D4W + 8*18  + o*3 + m], jcat[6][s],  a1);
                a1 = fmaf(W[O_D4W + 9*18  + o*3 + m], jcat[7][s],  a1);
                a2 = fmaf(W[O_D4W + 10*18 + o*3 + m], jcat[8][s],  a2);
                a2 = fmaf(W[O_D4W + 11*18 + o*3 + m], jcat[9][s],  a2);
                a2 = fmaf(W[O_D4W + 12*18 + o*3 + m], jcat[10][s], a2);
                a2 = fmaf(W[O_D4W + 13*18 + o*3 + m], jcat[11][s], a2);
            }
        }
        part[idx] = (a0 + a1) + a2;
    }
    __syncthreads();   // B2

    // ==== dec4 final: add 2-channel dc3 contribution and store ====
    if (tid < 90) {
        int o = tid / 15, t = tid % 15;
        float acc = part[tid];
        #pragma unroll
        for (int m = 0; m < 3; m++) {
            int s = t + 1 - m;
            if (s >= 0 && s < 15) {
                acc = fmaf(W[O_D4W + 0*18 + o*3 + m], dc3[0][s], acc);
                acc = fmaf(W[O_D4W + 1*18 + o*3 + m], dc3[1][s], acc);
            }
        }
        if (tid >= 2) out[tid - 2] = acc;
    }
}

extern "C" void kernel_launch(void* const* d_in, const int* in_sizes, int n_in,
                              void* d_out, int out_size) {
    (void)in_sizes; (void)n_in; (void)out_size;
    policy_kernel<<<1, 128>>>(
        (const float*)d_in[0],
        (const float*)d_in[1],  (const float*)d_in[2],
        (const float*)d_in[3],  (const float*)d_in[4],
        (const float*)d_in[5],  (const float*)d_in[6],
        (const float*)d_in[7],  (const float*)d_in[8],
        (const float*)d_in[9],  (const float*)d_in[10],
        (const float*)d_in[11], (const float*)d_in[12],
        (const float*)d_in[13], (const float*)d_in[14],
        (const float*)d_in[15], (const float*)d_in[16],
        (const float*)d_in[17], (const float*)d_in[18],
        (float*)d_out);
}